// round 14
// baseline (speedup 1.0000x reference)
#include <cuda_runtime.h>
#include <cuda_fp16.h>
#include <math.h>

#define Bn 4
#define DIMc 192
#define H3 576
#define HSp 128
#define NPIX 16384
#define HEADS 6
#define CPH 32

typedef unsigned long long u64;

#define FMA2(acc, a, b) \
    asm("fma.rn.f32x2 %0, %1, %2, %0;" : "+l"(acc) : "l"(a), "l"(b))
#define PACK2(d, lo, hi) \
    asm("mov.b64 %0, {%1, %2};" : "=l"(d) : "f"(lo), "f"(hi))
#define UNPACK2(lo, hi, v) \
    asm("mov.b64 {%0, %1}, %2;" : "=f"(lo), "=f"(hi) : "l"(v))

#define LDM_X4(R, addr) \
    asm volatile("ldmatrix.sync.aligned.m8n8.x4.shared.b16 {%0,%1,%2,%3}, [%4];" \
                 : "=r"((R)[0]), "=r"((R)[1]), "=r"((R)[2]), "=r"((R)[3]) : "r"(addr))
#define LDM_X4T(R, addr) \
    asm volatile("ldmatrix.sync.aligned.m8n8.x4.trans.shared.b16 {%0,%1,%2,%3}, [%4];" \
                 : "=r"((R)[0]), "=r"((R)[1]), "=r"((R)[2]), "=r"((R)[3]) : "r"(addr))
#define MMA_F16(C, A, b0, b1) \
    asm volatile("mma.sync.aligned.m16n8k16.row.col.f32.f16.f16.f32 " \
                 "{%0,%1,%2,%3},{%4,%5,%6,%7},{%8,%9},{%0,%1,%2,%3};" \
                 : "+f"((C)[0]), "+f"((C)[1]), "+f"((C)[2]), "+f"((C)[3]) \
                 : "r"((A)[0]), "r"((A)[1]), "r"((A)[2]), "r"((A)[3]), "r"(b0), "r"(b1))

#define CPA(dst, src) \
    asm volatile("cp.async.cg.shared.global [%0], [%1], 16;" :: "r"(dst), "l"(src))
#define CPC() asm volatile("cp.async.commit_group;")
#define CPW1() asm volatile("cp.async.wait_group 1;")
#define CPW0() asm volatile("cp.async.wait_group 0;")

// ---- scratch ----
__device__ float g_P[Bn * H3 * NPIX];
__device__ float g_D[Bn * H3 * NPIX];
__device__ float g_attn[Bn * HEADS * CPH * CPH];
__device__ float g_A[Bn * HEADS * CPH * CPH];
__device__ float g_normsq[Bn * 2 * DIMc];
__device__ __half g_XH[Bn * DIMc * 65536];
__device__ __half g_XL[Bn * DIMc * 65536];
__device__ __half g_WH[H3 * DIMc];
__device__ __half g_WL[H3 * DIMc];
__device__ __half g_PWH[DIMc * DIMc];
__device__ __half g_OH[Bn * DIMc * NPIX];
__device__ __half g_OL[Bn * DIMc * NPIX];

// dynamic smem layout (elements)
#define XSTRIDE 136
#define XELEMS (32 * XSTRIDE)
#define WSTRIDE 40
#define WELEMS (96 * WSTRIDE)
#define OFF_XH 0
#define OFF_XL (2 * XELEMS)
#define OFF_WH (4 * XELEMS)
#define OFF_WL (4 * XELEMS + 2 * WELEMS)
#define SM_GEMM_ELEMS (4 * XELEMS + 4 * WELEMS)
#define SMEM_QKV_BYTES (SM_GEMM_ELEMS * 2)            // sPool overlays stage smem
#define SMEM_PROJ_BYTES (SM_GEMM_ELEMS * 2)

// ------------------- split x into hi/lo fp16, pool-quad layout
__global__ void __launch_bounds__(256) k_splitX(const float* __restrict__ x) {
    int bk = blockIdx.x;
    const float* src = x + (size_t)bk * 65536;
    __half* dH = g_XH + (size_t)bk * 65536;
    __half* dL = g_XL + (size_t)bk * 65536;
#pragma unroll 4
    for (int i = 0; i < 64; i++) {
        int hp = threadIdx.x + i * 256;
        int hy = hp >> 7, hx = hp & 127;
        float2 a = *(const float2*)(src + (2 * hy) * 256 + 2 * hx);
        float2 bv = *(const float2*)(src + (2 * hy + 1) * 256 + 2 * hx);
        float v0 = a.x, v1 = bv.x, v2 = a.y, v3 = bv.y;
        __half h0 = __float2half_rn(v0), h1 = __float2half_rn(v1);
        __half h2 = __float2half_rn(v2), h3 = __float2half_rn(v3);
        __half2 H01, H23, L01, L23;
        H01.x = h0; H01.y = h1; H23.x = h2; H23.y = h3;
        L01.x = __float2half_rn(v0 - __half2float(h0));
        L01.y = __float2half_rn(v1 - __half2float(h1));
        L23.x = __float2half_rn(v2 - __half2float(h2));
        L23.y = __float2half_rn(v3 - __half2float(h3));
        *(__half2*)(dH + hp * 4) = H01;
        *(__half2*)(dH + hp * 4 + 2) = H23;
        *(__half2*)(dL + hp * 4) = L01;
        *(__half2*)(dL + hp * 4 + 2) = L23;
    }
}

// ------------------- split qkv_w (hi/lo), proj_w (hi only), zero accums
__global__ void k_splitW(const float* __restrict__ qw,
                         const float* __restrict__ pw) {
    int i = blockIdx.x * 256 + threadIdx.x;
    if (i < H3 * DIMc) {
        float v = qw[i];
        __half h = __float2half_rn(v);
        g_WH[i] = h;
        g_WL[i] = __float2half_rn(v - __half2float(h));
    }
    if (i < DIMc * DIMc) {
        g_PWH[i] = __float2half_rn(pw[i]);
    }
    if (i < Bn * HEADS * CPH * CPH) g_attn[i] = 0.f;
    if (i < Bn * 2 * DIMc)          g_normsq[i] = 0.f;
}

// ------------------------------------------- 1x1 qkv conv + 2x2 maxpool
// 96oc x 128px tile, 384 threads (12 warps: 3m x 4n) for occupancy.
// q,k blocks (ocb<4): 3-term fp16 split; v blocks (ocb>=4): 2-term.
__global__ void __launch_bounds__(384, 2) k_qkvpool() {
    extern __shared__ __half sm[];
    float* sPool = (float*)sm;        // overlays GEMM smem (dead after mainloop)

    int tid = threadIdx.x;
    int b = blockIdx.z;
    int oc0 = blockIdx.x * 96;
    bool doP3 = (blockIdx.x < 4);     // q,k need the W-residual pass; v doesn't
    int y = blockIdx.y >> 2, cblk = blockIdx.y & 3;
    int px0 = y * 512 + cblk * 128;

    int wid = tid >> 5, l = tid & 31;
    int wm = wid >> 2, wn = wid & 3;      // 3 x 4 warp grid
    int m0 = wm * 32, n0 = wn * 32;
    int arow = (l & 7) + ((l >> 3) & 1) * 8;
    int acol8 = (l >> 4) * 8;

    auto load_stage = [&](int s, int k0) {
        size_t xbase = (((size_t)b * DIMc + k0) << 16) + px0;
#pragma unroll
        for (int it = 0; it < 2; it++) {
            int idx = tid + it * 384;
            if (idx < 512) {
                int k = idx >> 4, c8 = (idx & 15) * 8;
                size_t off = xbase + ((size_t)k << 16) + c8;
                unsigned dH = (unsigned)__cvta_generic_to_shared(
                    sm + OFF_XH + s * XELEMS + k * XSTRIDE + c8);
                unsigned dL = (unsigned)__cvta_generic_to_shared(
                    sm + OFF_XL + s * XELEMS + k * XSTRIDE + c8);
                CPA(dH, g_XH + off);
                CPA(dL, g_XL + off);
            }
        }
        {
            int idx = tid;
            if (idx < 384) {
                int oc = idx >> 2, k8 = (idx & 3) * 8;
                size_t off = (size_t)(oc0 + oc) * DIMc + k0 + k8;
                unsigned dH = (unsigned)__cvta_generic_to_shared(
                    sm + OFF_WH + s * WELEMS + oc * WSTRIDE + k8);
                unsigned dL = (unsigned)__cvta_generic_to_shared(
                    sm + OFF_WL + s * WELEMS + oc * WSTRIDE + k8);
                CPA(dH, g_WH + off);
                CPA(dL, g_WL + off);
            }
        }
    };

    float c[2][4][4];
#pragma unroll
    for (int mf = 0; mf < 2; mf++)
#pragma unroll
        for (int j = 0; j < 4; j++)
#pragma unroll
            for (int q = 0; q < 4; q++) c[mf][j][q] = 0.f;

    load_stage(0, 0);
    CPC();

#pragma unroll 1
    for (int kc = 0; kc < 6; kc++) {
        int cur = kc & 1;
        if (kc < 5) { load_stage(cur ^ 1, (kc + 1) * 32); CPC(); CPW1(); }
        else        { CPW0(); }
        __syncthreads();
        const __half* xh = sm + OFF_XH + cur * XELEMS;
        const __half* xl = sm + OFF_XL + cur * XELEMS;
        const __half* wh = sm + OFF_WH + cur * WELEMS;
        const __half* wl = sm + OFF_WL + cur * WELEMS;
#pragma unroll
        for (int ks = 0; ks < 2; ks++) {
            unsigned aH[2][4], aL[2][4], bH[2][4], bL[2][4];
#pragma unroll
            for (int mf = 0; mf < 2; mf++) {
                LDM_X4(aH[mf], (unsigned)__cvta_generic_to_shared(
                    wh + (m0 + mf * 16 + arow) * WSTRIDE + ks * 16 + acol8));
                if (doP3)
                    LDM_X4(aL[mf], (unsigned)__cvta_generic_to_shared(
                        wl + (m0 + mf * 16 + arow) * WSTRIDE + ks * 16 + acol8));
            }
#pragma unroll
            for (int nb = 0; nb < 2; nb++) {
                LDM_X4T(bH[nb], (unsigned)__cvta_generic_to_shared(
                    xh + (ks * 16 + arow) * XSTRIDE + n0 + nb * 16 + acol8));
                LDM_X4T(bL[nb], (unsigned)__cvta_generic_to_shared(
                    xl + (ks * 16 + arow) * XSTRIDE + n0 + nb * 16 + acol8));
            }
#pragma unroll
            for (int mf = 0; mf < 2; mf++)
#pragma unroll
                for (int j = 0; j < 4; j++)
                    MMA_F16(c[mf][j], aH[mf],
                            bH[j >> 1][(j & 1) * 2], bH[j >> 1][(j & 1) * 2 + 1]);
#pragma unroll
            for (int mf = 0; mf < 2; mf++)
#pragma unroll
                for (int j = 0; j < 4; j++)
                    MMA_F16(c[mf][j], aH[mf],
                            bL[j >> 1][(j & 1) * 2], bL[j >> 1][(j & 1) * 2 + 1]);
            if (doP3) {
#pragma unroll
                for (int mf = 0; mf < 2; mf++)
#pragma unroll
                    for (int j = 0; j < 4; j++)
                        MMA_F16(c[mf][j], aL[mf],
                                bH[j >> 1][(j & 1) * 2], bH[j >> 1][(j & 1) * 2 + 1]);
            }
        }
        __syncthreads();
    }

#pragma unroll
    for (int mf = 0; mf < 2; mf++)
#pragma unroll
        for (int j = 0; j < 4; j++) {
            float v01 = fmaxf(c[mf][j][0], c[mf][j][1]);
            float v23 = fmaxf(c[mf][j][2], c[mf][j][3]);
            float p01 = fmaxf(v01, __shfl_xor_sync(0xffffffffu, v01, 1));
            float p23 = fmaxf(v23, __shfl_xor_sync(0xffffffffu, v23, 1));
            if (!(l & 1)) {
                int hp = wn * 8 + j * 2 + ((l & 2) >> 1);
                int rl = m0 + mf * 16 + (l >> 2);
                sPool[rl * 33 + hp] = p01;
                sPool[(rl + 8) * 33 + hp] = p23;
            }
        }
    __syncthreads();
#pragma unroll
    for (int it = 0; it < 8; it++) {
        int t = tid + it * 384;
        int ocl = t >> 5, hx = t & 31;
        g_P[((size_t)b * H3 + oc0 + ocl) * NPIX + y * HSp + cblk * 32 + hx] =
            sPool[ocl * 33 + hx];
    }
}

// ------------------------------------------------- depthwise 3x3 (SAME)
__global__ void __launch_bounds__(256) k_dw(const float* __restrict__ dww) {
    __shared__ float smh[18][132];
    int tid = threadIdx.x;
    int ch = blockIdx.y, b = blockIdx.z;
    int rg = blockIdx.x;
    int r0 = rg * 16;
    const float* src = g_P + ((size_t)b * H3 + ch) * NPIX;
    float*       dst = g_D + ((size_t)b * H3 + ch) * NPIX;
    float wgt[9];
#pragma unroll
    for (int i = 0; i < 9; i++) wgt[i] = dww[ch * 9 + i];

#pragma unroll
    for (int it = 0; it < 3; it++) {
        int idx = tid + it * 256;
        if (idx < 18 * 32) {
            int lr = idx >> 5, c4 = (idx & 31) * 4;
            int rr = r0 + lr - 1;
            float4 v = make_float4(0.f, 0.f, 0.f, 0.f);
            if (rr >= 0 && rr < 128)
                v = *(const float4*)(src + rr * 128 + c4);
            smh[lr][1 + c4] = v.x; smh[lr][2 + c4] = v.y;
            smh[lr][3 + c4] = v.z; smh[lr][4 + c4] = v.w;
            if (c4 == 0)  smh[lr][0] = 0.f;
            if (c4 == 124) smh[lr][129] = 0.f;
        }
    }
    __syncthreads();

    float ss = 0.f;
#pragma unroll
    for (int it = 0; it < 8; it++) {
        int p = tid + it * 256;
        int r = p >> 7, cc = p & 127;
        float s = 0.f;
#pragma unroll
        for (int dr = 0; dr < 3; dr++)
#pragma unroll
            for (int dc = 0; dc < 3; dc++)
                s = fmaf(wgt[dr * 3 + dc], smh[r + dr][cc + dc], s);
        dst[r0 * 128 + p] = s;
        ss = fmaf(s, s, ss);
    }
    if (ch < 2 * DIMc) {
#pragma unroll
        for (int o = 16; o > 0; o >>= 1) ss += __shfl_xor_sync(0xffffffffu, ss, o);
        __shared__ float red[8];
        if ((tid & 31) == 0) red[tid >> 5] = ss;
        __syncthreads();
        if (tid < 8) {
            float v = red[tid];
#pragma unroll
            for (int o = 4; o > 0; o >>= 1) v += __shfl_xor_sync(0xffu, v, o);
            if (tid == 0) atomicAdd(&g_normsq[b * 2 * DIMc + ch], v);
        }
    }
}

// ----------------------------------------- attn[b,h,c,d] = sum_n q k
__global__ void __launch_bounds__(256) k_attn() {
    __shared__ float qs[32][65];
    __shared__ float ks[32][65];
    int tid = threadIdx.x;
    int bh = blockIdx.y;
    int b = bh / HEADS, h = bh - b * HEADS;
    int n0 = blockIdx.x * 1024;
    const float* qb = g_D + ((size_t)b * H3 + h * CPH) * NPIX;
    const float* kb = g_D + ((size_t)b * H3 + DIMc + h * CPH) * NPIX;
    int dgi = tid & 7, cg = (tid >> 3) & 7, sl = tid >> 6;
    float acc[4][4];
#pragma unroll
    for (int i = 0; i < 4; i++)
#pragma unroll
        for (int j = 0; j < 4; j++) acc[i][j] = 0.f;

    for (int t = 0; t < 16; t++) {
        int n = n0 + t * 64;
#pragma unroll
        for (int it = 0; it < 2; it++) {
            int idx = tid + it * 256;
            int row = idx >> 4, n4 = (idx & 15) * 4;
            float4 q4 = *(const float4*)(qb + (size_t)row * NPIX + n + n4);
            float4 k4 = *(const float4*)(kb + (size_t)row * NPIX + n + n4);
            qs[row][n4 + 0] = q4.x; qs[row][n4 + 1] = q4.y;
            qs[row][n4 + 2] = q4.z; qs[row][n4 + 3] = q4.w;
            ks[row][n4 + 0] = k4.x; ks[row][n4 + 1] = k4.y;
            ks[row][n4 + 2] = k4.z; ks[row][n4 + 3] = k4.w;
        }
        __syncthreads();
#pragma unroll
        for (int nn = sl * 16; nn < sl * 16 + 16; nn++) {
            float qv[4], kv[4];
#pragma unroll
            for (int i = 0; i < 4; i++) qv[i] = qs[cg * 4 + i][nn];
#pragma unroll
            for (int j = 0; j < 4; j++) kv[j] = ks[dgi * 4 + j][nn];
#pragma unroll
            for (int i = 0; i < 4; i++)
#pragma unroll
                for (int j = 0; j < 4; j++)
                    acc[i][j] = fmaf(qv[i], kv[j], acc[i][j]);
        }
        __syncthreads();
    }
#pragma unroll
    for (int i = 0; i < 4; i++)
#pragma unroll
        for (int j = 0; j < 4; j++)
            atomicAdd(&g_attn[((size_t)bh * CPH + cg * 4 + i) * CPH + dgi * 4 + j],
                      acc[i][j]);
}

// --------------- normalize, temperature, 4x top-k masked softmax, combine
__global__ void __launch_bounds__(256) k_soft(const float* __restrict__ temp,
                                              const float* __restrict__ a1,
                                              const float* __restrict__ a2,
                                              const float* __restrict__ a3,
                                              const float* __restrict__ a4) {
    int lane = threadIdx.x & 31;
    int wid = blockIdx.x * 8 + (threadIdx.x >> 5);
    int bh = wid >> 5, c = wid & 31;
    int b = bh / HEADS, h = bh - b * HEADS;
    float v = g_attn[((size_t)bh * CPH + c) * CPH + lane];
    float nq = fmaxf(sqrtf(g_normsq[b * 2 * DIMc + h * CPH + c]), 1e-12f);
    float nk = fmaxf(sqrtf(g_normsq[b * 2 * DIMc + DIMc + h * CPH + lane]), 1e-12f);
    v = v / (nq * nk) * temp[h];
    int rank = 0;
#pragma unroll
    for (int j = 0; j < 32; j++) {
        float vj = __shfl_sync(0xffffffffu, v, j);
        rank += (vj > v || (vj == v && j < lane)) ? 1 : 0;
    }
    float m = v;
#pragma unroll
    for (int o = 16; o > 0; o >>= 1) m = fmaxf(m, __shfl_xor_sync(0xffffffffu, m, o));
    float e = expf(v - m);
    float e16 = rank < 16 ? e : 0.f;
    float e21 = rank < 21 ? e : 0.f;
    float e24 = rank < 24 ? e : 0.f;
    float e25 = rank < 25 ? e : 0.f;
    float s16 = e16, s21 = e21, s24 = e24, s25 = e25;
#pragma unroll
    for (int o = 16; o > 0; o >>= 1) {
        s16 += __shfl_xor_sync(0xffffffffu, s16, o);
        s21 += __shfl_xor_sync(0xffffffffu, s21, o);
        s24 += __shfl_xor_sync(0xffffffffu, s24, o);
        s25 += __shfl_xor_sync(0xffffffffu, s25, o);
    }
    float r = e16 * (a1[0] / s16) + e21 * (a2[0] / s21) +
              e24 * (a3[0] / s24) + e25 * (a4[0] / s25);
    g_A[((size_t)bh * CPH + c) * CPH + lane] = r;
}

// ------------------- out = gelu(A @ v), written as fp16 hi/lo for proj
__global__ void __launch_bounds__(256) k_av() {
    __shared__ float sA[1024];
    int tid = threadIdx.x;
    int bh = blockIdx.y;
    int b = bh / HEADS, h = bh - b * HEADS;
#pragma unroll
    for (int it = 0; it < 4; it++)
        sA[tid + it * 256] = g_A[(size_t)bh * 1024 + tid + it * 256];
    __syncthreads();
    int n = blockIdx.x * 256 + tid;
    const float* vb = g_D + ((size_t)b * H3 + 2 * DIMc + h * CPH) * NPIX + n;
    u64 vp[16];
#pragma unroll
    for (int d = 0; d < 16; d++) {
        float v0 = vb[(size_t)(2 * d) * NPIX];
        float v1 = vb[(size_t)(2 * d + 1) * NPIX];
        PACK2(vp[d], v0, v1);
    }
    size_t ob = ((size_t)b * DIMc + h * CPH) * NPIX + n;
#pragma unroll
    for (int c2 = 0; c2 < 32; c2++) {
        u64 acc = 0ull;
        const u64* ap = (const u64*)(&sA[c2 * 32]);
#pragma unroll
        for (int d = 0; d < 16; d++)
            FMA2(acc, ap[d], vp[d]);
        float lo, hi;
        UNPACK2(lo, hi, acc);
        float s = lo + hi;
        s = s * normcdff(s);
        __half hh = __float2half_rn(s);
        g_OH[ob + (size_t)c2 * NPIX] = hh;
        g_OL[ob + (size_t)c2 * NPIX] = __float2half_rn(s - __half2float(hh));
    }
}

// -------------------- proj 1x1, pipelined HMMA (2-term fp16), upsample-fused
__global__ void __launch_bounds__(256) k_proj(float* __restrict__ out) {
    extern __shared__ __half sm[];

    int tid = threadIdx.x;
    int b = blockIdx.z;
    int oc0 = blockIdx.y * 96;
    int n0 = blockIdx.x * 128;
    int hy = blockIdx.x;

    int wid = tid >> 5, l = tid & 31;
    int wm = wid & 1, wn = wid >> 1;
    int m0 = wm * 48, nw0 = wn * 32;
    int arow = (l & 7) + ((l >> 3) & 1) * 8;
    int acol8 = (l >> 4) * 8;

    int xk = tid >> 4, xc8 = (tid & 15) * 8;

    auto load_stage = [&](int s, int k0) {
#pragma unroll
        for (int it = 0; it < 2; it++) {
            int k = xk + it * 16;
            size_t off = ((size_t)b * DIMc + k0 + k) * NPIX + n0 + xc8;
            unsigned dH = (unsigned)__cvta_generic_to_shared(
                sm + OFF_XH + s * XELEMS + k * XSTRIDE + xc8);
            unsigned dL = (unsigned)__cvta_generic_to_shared(
                sm + OFF_XL + s * XELEMS + k * XSTRIDE + xc8);
            CPA(dH, g_OH + off);
            CPA(dL, g_OL + off);
        }
#pragma unroll
        for (int it = 0; it < 2; it++) {
            int idx = tid + it * 256;
            if (idx < 384) {
                int oc = idx >> 2, k8 = (idx & 3) * 8;
                size_t off = (size_t)(oc0 + oc) * DIMc + k0 + k8;
                unsigned dH = (unsigned)__cvta_generic_to_shared(
                    sm + OFF_WH + s * WELEMS + oc * WSTRIDE + k8);
                CPA(dH, g_PWH + off);
            }
        }
    };

    float c[3][4][4];
#pragma unroll
    for (int mf = 0; mf < 3; mf++)
#pragma unroll
        for (int j = 0; j < 4; j++)
#pragma unroll
            for (int q = 0; q < 4; q++) c[mf][j][q] = 0.f;

    load_stage(0, 0);
    CPC();

#pragma unroll 1
    for (int kc = 0; kc < 6; kc++) {
        int cur = kc & 1;
        if (kc < 5) { load_stage(cur ^ 1, (kc + 1) * 32); CPC(); CPW1(); }
        else        { CPW0(); }
        __syncthreads();
        const __half* xh = sm + OFF_XH + cur * XELEMS;
        const __half* xl = sm + OFF_XL + cur * XELEMS;
        const __half* wh = sm + OFF_WH + cur * WELEMS;
#pragma unroll
        for (int ks = 0; ks < 2; ks++) {
            unsigned aH[3][4], bH[2][4], bL[2][4];
#pragma unroll
            for (int mf = 0; mf < 3; mf++)
                LDM_X4(aH[mf], (unsigned)__cvta_generic_to_shared(
                    wh + (m0 + mf * 16 + arow) * WSTRIDE + ks * 16 + acol8));
#pragma unroll
            for (int nb = 0; nb < 2; nb++) {
                LDM_X4T(bH[nb], (unsigned)__cvta_generic_to_shared(
                    xh + (ks * 16 + arow) * XSTRIDE + nw0 + nb * 16 + acol8));
                LDM_X4T(bL[nb], (unsigned)__cvta_generic_to_shared(
                    xl + (ks * 16 + arow) * XSTRIDE + nw0 + nb * 16 + acol8));
            }
#pragma unroll
            for (int mf = 0; mf < 3; mf++)
#pragma unroll
                for (int j = 0; j < 4; j++)
                    MMA_F16(c[mf][j], aH[mf],
                            bH[j >> 1][(j & 1) * 2], bH[j >> 1][(j & 1) * 2 + 1]);
#pragma unroll
            for (int mf = 0; mf < 3; mf++)
#pragma unroll
                for (int j = 0; j < 4; j++)
                    MMA_F16(c[mf][j], aH[mf],
                            bL[j >> 1][(j & 1) * 2], bL[j >> 1][(j & 1) * 2 + 1]);
        }
        __syncthreads();
    }

    int fr0 = 2 * hy;
#pragma unroll
    for (int mf = 0; mf < 3; mf++)
#pragma unroll
        for (int j = 0; j < 4; j++)
#pragma unroll
            for (int rh = 0; rh < 2; rh++) {
                float v0 = c[mf][j][rh * 2 + 0];
                float v1 = c[mf][j][rh * 2 + 1];
                int oc = oc0 + m0 + mf * 16 + (l >> 2) + 8 * rh;
                int hc = nw0 + (j >> 1) * 16 + (j & 1) * 8 + 2 * (l & 3);
                float4 v4 = make_float4(v0, v0, v1, v1);
                float* ob = out + ((size_t)b * DIMc + oc) * 65536 +
                            fr0 * 256 + 2 * hc;
                *(float4*)ob = v4;
                *(float4*)(ob + 256) = v4;
            }
}

// ---------------------------------------------------------------- launch
extern "C" void kernel_launch(void* const* d_in, const int* in_sizes, int n_in,
                              void* d_out, int out_size) {
    const float* x      = (const float*)d_in[0];
    const float* temp   = (const float*)d_in[1];
    const float* qkv_w  = (const float*)d_in[2];
    const float* dw_w   = (const float*)d_in[3];
    const float* proj_w = (const float*)d_in[4];
    const float* a1 = (const float*)d_in[5];
    const float* a2 = (const float*)d_in[6];
    const float* a3 = (const float*)d_in[7];
    const float* a4 = (const float*)d_in[8];
    float* out = (float*)d_out;

    cudaFuncSetAttribute(k_qkvpool, cudaFuncAttributeMaxDynamicSharedMemorySize,
                         SMEM_QKV_BYTES);
    cudaFuncSetAttribute(k_proj, cudaFuncAttributeMaxDynamicSharedMemorySize,
                         SMEM_PROJ_BYTES);

    k_splitX<<<Bn * DIMc, 256>>>(x);
    k_splitW<<<432, 256>>>(qkv_w, proj_w);
    k_qkvpool<<<dim3(6, 512, 4), 384, SMEM_QKV_BYTES>>>();
    k_dw<<<dim3(8, 576, 4), 256>>>(dw_w);
    k_attn<<<dim3(16, 24), 256>>>();
    k_soft<<<96, 256>>>(temp, a1, a2, a3, a4);
    k_av<<<dim3(64, 24), 256>>>();
    k_proj<<<dim3(128, 2, 4), 256, SMEM_PROJ_BYTES>>>(out);
}

// round 15
// speedup vs baseline: 1.5278x; 1.5278x over previous
#include <cuda_runtime.h>
#include <cuda_fp16.h>
#include <math.h>

#define Bn 4
#define DIMc 192
#define H3 576
#define HSp 128
#define NPIX 16384
#define HEADS 6
#define CPH 32

typedef unsigned long long u64;

#define FMA2(acc, a, b) \
    asm("fma.rn.f32x2 %0, %1, %2, %0;" : "+l"(acc) : "l"(a), "l"(b))
#define PACK2(d, lo, hi) \
    asm("mov.b64 %0, {%1, %2};" : "=l"(d) : "f"(lo), "f"(hi))
#define UNPACK2(lo, hi, v) \
    asm("mov.b64 {%0, %1}, %2;" : "=f"(lo), "=f"(hi) : "l"(v))

#define LDM_X4(R, addr) \
    asm volatile("ldmatrix.sync.aligned.m8n8.x4.shared.b16 {%0,%1,%2,%3}, [%4];" \
                 : "=r"((R)[0]), "=r"((R)[1]), "=r"((R)[2]), "=r"((R)[3]) : "r"(addr))
#define LDM_X4T(R, addr) \
    asm volatile("ldmatrix.sync.aligned.m8n8.x4.trans.shared.b16 {%0,%1,%2,%3}, [%4];" \
                 : "=r"((R)[0]), "=r"((R)[1]), "=r"((R)[2]), "=r"((R)[3]) : "r"(addr))
#define MMA_F16(C, A, b0, b1) \
    asm volatile("mma.sync.aligned.m16n8k16.row.col.f32.f16.f16.f32 " \
                 "{%0,%1,%2,%3},{%4,%5,%6,%7},{%8,%9},{%0,%1,%2,%3};" \
                 : "+f"((C)[0]), "+f"((C)[1]), "+f"((C)[2]), "+f"((C)[3]) \
                 : "r"((A)[0]), "r"((A)[1]), "r"((A)[2]), "r"((A)[3]), "r"(b0), "r"(b1))

#define CPA(dst, src) \
    asm volatile("cp.async.cg.shared.global [%0], [%1], 16;" :: "r"(dst), "l"(src))
#define CPC() asm volatile("cp.async.commit_group;")
#define CPW1() asm volatile("cp.async.wait_group 1;")
#define CPW0() asm volatile("cp.async.wait_group 0;")

// ---- scratch ----
__device__ float g_P[Bn * H3 * NPIX];
__device__ float g_D[Bn * H3 * NPIX];
__device__ float g_attn[Bn * HEADS * CPH * CPH];
__device__ float g_A[Bn * HEADS * CPH * CPH];
__device__ float g_normsq[Bn * 2 * DIMc];
__device__ __half g_XH[Bn * DIMc * 65536];
__device__ __half g_XL[Bn * DIMc * 65536];
__device__ __half g_WH[H3 * DIMc];
__device__ __half g_WL[H3 * DIMc];
__device__ __half g_PWH[DIMc * DIMc];
__device__ __half g_OH[Bn * DIMc * NPIX];
__device__ __half g_OL[Bn * DIMc * NPIX];

// dynamic smem layout (elements)
#define XSTRIDE 136
#define XELEMS (32 * XSTRIDE)
#define WSTRIDE 40
#define WELEMS (96 * WSTRIDE)
#define OFF_XH 0
#define OFF_XL (2 * XELEMS)
#define OFF_WH (4 * XELEMS)
#define OFF_WL (4 * XELEMS + 2 * WELEMS)
#define SM_GEMM_ELEMS (4 * XELEMS + 4 * WELEMS)
#define SMEM_QKV_BYTES (SM_GEMM_ELEMS * 2)            // sPool overlays stage smem
#define SMEM_PROJ_BYTES (SM_GEMM_ELEMS * 2)

// ------------------- split x into hi/lo fp16, pool-quad layout
__global__ void __launch_bounds__(256) k_splitX(const float* __restrict__ x) {
    int bk = blockIdx.x;
    const float* src = x + (size_t)bk * 65536;
    __half* dH = g_XH + (size_t)bk * 65536;
    __half* dL = g_XL + (size_t)bk * 65536;
#pragma unroll 4
    for (int i = 0; i < 64; i++) {
        int hp = threadIdx.x + i * 256;
        int hy = hp >> 7, hx = hp & 127;
        float2 a = *(const float2*)(src + (2 * hy) * 256 + 2 * hx);
        float2 bv = *(const float2*)(src + (2 * hy + 1) * 256 + 2 * hx);
        float v0 = a.x, v1 = bv.x, v2 = a.y, v3 = bv.y;
        __half h0 = __float2half_rn(v0), h1 = __float2half_rn(v1);
        __half h2 = __float2half_rn(v2), h3 = __float2half_rn(v3);
        __half2 H01, H23, L01, L23;
        H01.x = h0; H01.y = h1; H23.x = h2; H23.y = h3;
        L01.x = __float2half_rn(v0 - __half2float(h0));
        L01.y = __float2half_rn(v1 - __half2float(h1));
        L23.x = __float2half_rn(v2 - __half2float(h2));
        L23.y = __float2half_rn(v3 - __half2float(h3));
        *(__half2*)(dH + hp * 4) = H01;
        *(__half2*)(dH + hp * 4 + 2) = H23;
        *(__half2*)(dL + hp * 4) = L01;
        *(__half2*)(dL + hp * 4 + 2) = L23;
    }
}

// ------------------- split qkv_w (hi/lo), proj_w (hi only), zero accums
__global__ void k_splitW(const float* __restrict__ qw,
                         const float* __restrict__ pw) {
    int i = blockIdx.x * 256 + threadIdx.x;
    if (i < H3 * DIMc) {
        float v = qw[i];
        __half h = __float2half_rn(v);
        g_WH[i] = h;
        g_WL[i] = __float2half_rn(v - __half2float(h));
    }
    if (i < DIMc * DIMc) {
        g_PWH[i] = __float2half_rn(pw[i]);
    }
    if (i < Bn * HEADS * CPH * CPH) g_attn[i] = 0.f;
    if (i < Bn * 2 * DIMc)          g_normsq[i] = 0.f;
}

// ------------------------------------------- 1x1 qkv conv + 2x2 maxpool
// R12 config (known 443us): 256 threads, no reg cap.
// q,k blocks (ocb<4): 3-term fp16 split; v blocks (ocb>=4): 2-term.
__global__ void __launch_bounds__(256) k_qkvpool() {
    extern __shared__ __half sm[];
    float* sPool = (float*)sm;        // overlays GEMM smem (dead after mainloop)

    int tid = threadIdx.x;
    int b = blockIdx.z;
    int oc0 = blockIdx.x * 96;
    bool doP3 = (blockIdx.x < 4);
    int y = blockIdx.y >> 2, cblk = blockIdx.y & 3;
    int px0 = y * 512 + cblk * 128;

    int wid = tid >> 5, l = tid & 31;
    int wm = wid & 1, wn = wid >> 1;
    int m0 = wm * 48, n0 = wn * 32;
    int arow = (l & 7) + ((l >> 3) & 1) * 8;
    int acol8 = (l >> 4) * 8;

    int xk = tid >> 4, xc8 = (tid & 15) * 8;

    auto load_stage = [&](int s, int k0) {
        size_t xbase = (((size_t)b * DIMc + k0) << 16) + px0;
#pragma unroll
        for (int it = 0; it < 2; it++) {
            int k = xk + it * 16;
            size_t off = xbase + ((size_t)k << 16) + xc8;
            unsigned dH = (unsigned)__cvta_generic_to_shared(
                sm + OFF_XH + s * XELEMS + k * XSTRIDE + xc8);
            unsigned dL = (unsigned)__cvta_generic_to_shared(
                sm + OFF_XL + s * XELEMS + k * XSTRIDE + xc8);
            CPA(dH, g_XH + off);
            CPA(dL, g_XL + off);
        }
#pragma unroll
        for (int it = 0; it < 2; it++) {
            int idx = tid + it * 256;
            if (idx < 384) {
                int oc = idx >> 2, k8 = (idx & 3) * 8;
                size_t off = (size_t)(oc0 + oc) * DIMc + k0 + k8;
                unsigned dH = (unsigned)__cvta_generic_to_shared(
                    sm + OFF_WH + s * WELEMS + oc * WSTRIDE + k8);
                unsigned dL = (unsigned)__cvta_generic_to_shared(
                    sm + OFF_WL + s * WELEMS + oc * WSTRIDE + k8);
                CPA(dH, g_WH + off);
                CPA(dL, g_WL + off);
            }
        }
    };

    float c[3][4][4];
#pragma unroll
    for (int mf = 0; mf < 3; mf++)
#pragma unroll
        for (int j = 0; j < 4; j++)
#pragma unroll
            for (int q = 0; q < 4; q++) c[mf][j][q] = 0.f;

    load_stage(0, 0);
    CPC();

#pragma unroll 1
    for (int kc = 0; kc < 6; kc++) {
        int cur = kc & 1;
        if (kc < 5) { load_stage(cur ^ 1, (kc + 1) * 32); CPC(); CPW1(); }
        else        { CPW0(); }
        __syncthreads();
        const __half* xh = sm + OFF_XH + cur * XELEMS;
        const __half* xl = sm + OFF_XL + cur * XELEMS;
        const __half* wh = sm + OFF_WH + cur * WELEMS;
        const __half* wl = sm + OFF_WL + cur * WELEMS;
#pragma unroll
        for (int ks = 0; ks < 2; ks++) {
            unsigned aH[3][4], aL[3][4], bH[2][4], bL[2][4];
#pragma unroll
            for (int mf = 0; mf < 3; mf++) {
                LDM_X4(aH[mf], (unsigned)__cvta_generic_to_shared(
                    wh + (m0 + mf * 16 + arow) * WSTRIDE + ks * 16 + acol8));
                if (doP3)
                    LDM_X4(aL[mf], (unsigned)__cvta_generic_to_shared(
                        wl + (m0 + mf * 16 + arow) * WSTRIDE + ks * 16 + acol8));
            }
#pragma unroll
            for (int nb = 0; nb < 2; nb++) {
                LDM_X4T(bH[nb], (unsigned)__cvta_generic_to_shared(
                    xh + (ks * 16 + arow) * XSTRIDE + n0 + nb * 16 + acol8));
                LDM_X4T(bL[nb], (unsigned)__cvta_generic_to_shared(
                    xl + (ks * 16 + arow) * XSTRIDE + n0 + nb * 16 + acol8));
            }
#pragma unroll
            for (int mf = 0; mf < 3; mf++)
#pragma unroll
                for (int j = 0; j < 4; j++)
                    MMA_F16(c[mf][j], aH[mf],
                            bH[j >> 1][(j & 1) * 2], bH[j >> 1][(j & 1) * 2 + 1]);
#pragma unroll
            for (int mf = 0; mf < 3; mf++)
#pragma unroll
                for (int j = 0; j < 4; j++)
                    MMA_F16(c[mf][j], aH[mf],
                            bL[j >> 1][(j & 1) * 2], bL[j >> 1][(j & 1) * 2 + 1]);
            if (doP3) {
#pragma unroll
                for (int mf = 0; mf < 3; mf++)
#pragma unroll
                    for (int j = 0; j < 4; j++)
                        MMA_F16(c[mf][j], aL[mf],
                                bH[j >> 1][(j & 1) * 2], bH[j >> 1][(j & 1) * 2 + 1]);
            }
        }
        __syncthreads();
    }

#pragma unroll
    for (int mf = 0; mf < 3; mf++)
#pragma unroll
        for (int j = 0; j < 4; j++) {
            float v01 = fmaxf(c[mf][j][0], c[mf][j][1]);
            float v23 = fmaxf(c[mf][j][2], c[mf][j][3]);
            float p01 = fmaxf(v01, __shfl_xor_sync(0xffffffffu, v01, 1));
            float p23 = fmaxf(v23, __shfl_xor_sync(0xffffffffu, v23, 1));
            if (!(l & 1)) {
                int hp = wn * 8 + j * 2 + ((l & 2) >> 1);
                int rl = m0 + mf * 16 + (l >> 2);
                sPool[rl * 33 + hp] = p01;
                sPool[(rl + 8) * 33 + hp] = p23;
            }
        }
    __syncthreads();
#pragma unroll
    for (int it = 0; it < 12; it++) {
        int t = tid + it * 256;
        int ocl = t >> 5, hx = t & 31;
        g_P[((size_t)b * H3 + oc0 + ocl) * NPIX + y * HSp + cblk * 32 + hx] =
            sPool[ocl * 33 + hx];
    }
}

// ------------------------------------------------- depthwise 3x3 (SAME)
// register-rolling: 3 LDS per output (was 9). 128 cols x 2 rowgroups of 8.
__global__ void __launch_bounds__(256) k_dw(const float* __restrict__ dww) {
    __shared__ float smh[18][132];
    int tid = threadIdx.x;
    int ch = blockIdx.y, b = blockIdx.z;
    int rg = blockIdx.x;
    int r0 = rg * 16;
    const float* src = g_P + ((size_t)b * H3 + ch) * NPIX;
    float*       dst = g_D + ((size_t)b * H3 + ch) * NPIX;
    float wgt[9];
#pragma unroll
    for (int i = 0; i < 9; i++) wgt[i] = dww[ch * 9 + i];

#pragma unroll
    for (int it = 0; it < 3; it++) {
        int idx = tid + it * 256;
        if (idx < 18 * 32) {
            int lr = idx >> 5, c4 = (idx & 31) * 4;
            int rr = r0 + lr - 1;
            float4 v = make_float4(0.f, 0.f, 0.f, 0.f);
            if (rr >= 0 && rr < 128)
                v = *(const float4*)(src + rr * 128 + c4);
            smh[lr][1 + c4] = v.x; smh[lr][2 + c4] = v.y;
            smh[lr][3 + c4] = v.z; smh[lr][4 + c4] = v.w;
            if (c4 == 0)  smh[lr][0] = 0.f;
            if (c4 == 124) smh[lr][129] = 0.f;
        }
    }
    __syncthreads();

    int cc = tid & 127;            // output column
    int g = tid >> 7;              // rowgroup 0/1
    int base = g * 8;              // smem row of first window top
    float r0w[3], r1w[3];
#pragma unroll
    for (int d = 0; d < 3; d++) {
        r0w[d] = smh[base][cc + d];
        r1w[d] = smh[base + 1][cc + d];
    }
    float ss = 0.f;
#pragma unroll
    for (int rr = 0; rr < 8; rr++) {
        float r2w[3];
#pragma unroll
        for (int d = 0; d < 3; d++) r2w[d] = smh[base + rr + 2][cc + d];
        float s = 0.f;
#pragma unroll
        for (int d = 0; d < 3; d++) {
            s = fmaf(wgt[d], r0w[d], s);
            s = fmaf(wgt[3 + d], r1w[d], s);
            s = fmaf(wgt[6 + d], r2w[d], s);
        }
        dst[(r0 + g * 8 + rr) * 128 + cc] = s;
        ss = fmaf(s, s, ss);
#pragma unroll
        for (int d = 0; d < 3; d++) { r0w[d] = r1w[d]; r1w[d] = r2w[d]; }
    }

    if (ch < 2 * DIMc) {
#pragma unroll
        for (int o = 16; o > 0; o >>= 1) ss += __shfl_xor_sync(0xffffffffu, ss, o);
        __shared__ float red[8];
        if ((tid & 31) == 0) red[tid >> 5] = ss;
        __syncthreads();
        if (tid < 8) {
            float v = red[tid];
#pragma unroll
            for (int o = 4; o > 0; o >>= 1) v += __shfl_xor_sync(0xffu, v, o);
            if (tid == 0) atomicAdd(&g_normsq[b * 2 * DIMc + ch], v);
        }
    }
}

// ----------------------------------------- attn[b,h,c,d] = sum_n q k
__global__ void __launch_bounds__(256) k_attn() {
    __shared__ float qs[32][65];
    __shared__ float ks[32][65];
    int tid = threadIdx.x;
    int bh = blockIdx.y;
    int b = bh / HEADS, h = bh - b * HEADS;
    int n0 = blockIdx.x * 1024;
    const float* qb = g_D + ((size_t)b * H3 + h * CPH) * NPIX;
    const float* kb = g_D + ((size_t)b * H3 + DIMc + h * CPH) * NPIX;
    int dgi = tid & 7, cg = (tid >> 3) & 7, sl = tid >> 6;
    float acc[4][4];
#pragma unroll
    for (int i = 0; i < 4; i++)
#pragma unroll
        for (int j = 0; j < 4; j++) acc[i][j] = 0.f;

    for (int t = 0; t < 16; t++) {
        int n = n0 + t * 64;
#pragma unroll
        for (int it = 0; it < 2; it++) {
            int idx = tid + it * 256;
            int row = idx >> 4, n4 = (idx & 15) * 4;
            float4 q4 = *(const float4*)(qb + (size_t)row * NPIX + n + n4);
            float4 k4 = *(const float4*)(kb + (size_t)row * NPIX + n + n4);
            qs[row][n4 + 0] = q4.x; qs[row][n4 + 1] = q4.y;
            qs[row][n4 + 2] = q4.z; qs[row][n4 + 3] = q4.w;
            ks[row][n4 + 0] = k4.x; ks[row][n4 + 1] = k4.y;
            ks[row][n4 + 2] = k4.z; ks[row][n4 + 3] = k4.w;
        }
        __syncthreads();
#pragma unroll
        for (int nn = sl * 16; nn < sl * 16 + 16; nn++) {
            float qv[4], kv[4];
#pragma unroll
            for (int i = 0; i < 4; i++) qv[i] = qs[cg * 4 + i][nn];
#pragma unroll
            for (int j = 0; j < 4; j++) kv[j] = ks[dgi * 4 + j][nn];
#pragma unroll
            for (int i = 0; i < 4; i++)
#pragma unroll
                for (int j = 0; j < 4; j++)
                    acc[i][j] = fmaf(qv[i], kv[j], acc[i][j]);
        }
        __syncthreads();
    }
#pragma unroll
    for (int i = 0; i < 4; i++)
#pragma unroll
        for (int j = 0; j < 4; j++)
            atomicAdd(&g_attn[((size_t)bh * CPH + cg * 4 + i) * CPH + dgi * 4 + j],
                      acc[i][j]);
}

// --------------- normalize, temperature, 4x top-k masked softmax, combine
__global__ void __launch_bounds__(256) k_soft(const float* __restrict__ temp,
                                              const float* __restrict__ a1,
                                              const float* __restrict__ a2,
                                              const float* __restrict__ a3,
                                              const float* __restrict__ a4) {
    int lane = threadIdx.x & 31;
    int wid = blockIdx.x * 8 + (threadIdx.x >> 5);
    int bh = wid >> 5, c = wid & 31;
    int b = bh / HEADS, h = bh - b * HEADS;
    float v = g_attn[((size_t)bh * CPH + c) * CPH + lane];
    float nq = fmaxf(sqrtf(g_normsq[b * 2 * DIMc + h * CPH + c]), 1e-12f);
    float nk = fmaxf(sqrtf(g_normsq[b * 2 * DIMc + DIMc + h * CPH + lane]), 1e-12f);
    v = v / (nq * nk) * temp[h];
    int rank = 0;
#pragma unroll
    for (int j = 0; j < 32; j++) {
        float vj = __shfl_sync(0xffffffffu, v, j);
        rank += (vj > v || (vj == v && j < lane)) ? 1 : 0;
    }
    float m = v;
#pragma unroll
    for (int o = 16; o > 0; o >>= 1) m = fmaxf(m, __shfl_xor_sync(0xffffffffu, m, o));
    float e = expf(v - m);
    float e16 = rank < 16 ? e : 0.f;
    float e21 = rank < 21 ? e : 0.f;
    float e24 = rank < 24 ? e : 0.f;
    float e25 = rank < 25 ? e : 0.f;
    float s16 = e16, s21 = e21, s24 = e24, s25 = e25;
#pragma unroll
    for (int o = 16; o > 0; o >>= 1) {
        s16 += __shfl_xor_sync(0xffffffffu, s16, o);
        s21 += __shfl_xor_sync(0xffffffffu, s21, o);
        s24 += __shfl_xor_sync(0xffffffffu, s24, o);
        s25 += __shfl_xor_sync(0xffffffffu, s25, o);
    }
    float r = e16 * (a1[0] / s16) + e21 * (a2[0] / s21) +
              e24 * (a3[0] / s24) + e25 * (a4[0] / s25);
    g_A[((size_t)bh * CPH + c) * CPH + lane] = r;
}

// ------------------- out = gelu(A @ v), written as fp16 hi/lo for proj
__global__ void __launch_bounds__(256) k_av() {
    __shared__ float sA[1024];
    int tid = threadIdx.x;
    int bh = blockIdx.y;
    int b = bh / HEADS, h = bh - b * HEADS;
#pragma unroll
    for (int it = 0; it < 4; it++)
        sA[tid + it * 256] = g_A[(size_t)bh * 1024 + tid + it * 256];
    __syncthreads();
    int n = blockIdx.x * 256 + tid;
    const float* vb = g_D + ((size_t)b * H3 + 2 * DIMc + h * CPH) * NPIX + n;
    u64 vp[16];
#pragma unroll
    for (int d = 0; d < 16; d++) {
        float v0 = vb[(size_t)(2 * d) * NPIX];
        float v1 = vb[(size_t)(2 * d + 1) * NPIX];
        PACK2(vp[d], v0, v1);
    }
    size_t ob = ((size_t)b * DIMc + h * CPH) * NPIX + n;
#pragma unroll
    for (int c2 = 0; c2 < 32; c2++) {
        u64 acc = 0ull;
        const u64* ap = (const u64*)(&sA[c2 * 32]);
#pragma unroll
        for (int d = 0; d < 16; d++)
            FMA2(acc, ap[d], vp[d]);
        float lo, hi;
        UNPACK2(lo, hi, acc);
        float s = lo + hi;
        s = s * normcdff(s);
        __half hh = __float2half_rn(s);
        g_OH[ob + (size_t)c2 * NPIX] = hh;
        g_OL[ob + (size_t)c2 * NPIX] = __float2half_rn(s - __half2float(hh));
    }
}

// -------------------- proj 1x1, pipelined HMMA (2-term fp16), upsample-fused
__global__ void __launch_bounds__(256) k_proj(float* __restrict__ out) {
    extern __shared__ __half sm[];

    int tid = threadIdx.x;
    int b = blockIdx.z;
    int oc0 = blockIdx.y * 96;
    int n0 = blockIdx.x * 128;
    int hy = blockIdx.x;

    int wid = tid >> 5, l = tid & 31;
    int wm = wid & 1, wn = wid >> 1;
    int m0 = wm * 48, nw0 = wn * 32;
    int arow = (l & 7) + ((l >> 3) & 1) * 8;
    int acol8 = (l >> 4) * 8;

    int xk = tid >> 4, xc8 = (tid & 15) * 8;

    auto load_stage = [&](int s, int k0) {
#pragma unroll
        for (int it = 0; it < 2; it++) {
            int k = xk + it * 16;
            size_t off = ((size_t)b * DIMc + k0 + k) * NPIX + n0 + xc8;
            unsigned dH = (unsigned)__cvta_generic_to_shared(
                sm + OFF_XH + s * XELEMS + k * XSTRIDE + xc8);
            unsigned dL = (unsigned)__cvta_generic_to_shared(
                sm + OFF_XL + s * XELEMS + k * XSTRIDE + xc8);
            CPA(dH, g_OH + off);
            CPA(dL, g_OL + off);
        }
#pragma unroll
        for (int it = 0; it < 2; it++) {
            int idx = tid + it * 256;
            if (idx < 384) {
                int oc = idx >> 2, k8 = (idx & 3) * 8;
                size_t off = (size_t)(oc0 + oc) * DIMc + k0 + k8;
                unsigned dH = (unsigned)__cvta_generic_to_shared(
                    sm + OFF_WH + s * WELEMS + oc * WSTRIDE + k8);
                CPA(dH, g_PWH + off);
            }
        }
    };

    float c[3][4][4];
#pragma unroll
    for (int mf = 0; mf < 3; mf++)
#pragma unroll
        for (int j = 0; j < 4; j++)
#pragma unroll
            for (int q = 0; q < 4; q++) c[mf][j][q] = 0.f;

    load_stage(0, 0);
    CPC();

#pragma unroll 1
    for (int kc = 0; kc < 6; kc++) {
        int cur = kc & 1;
        if (kc < 5) { load_stage(cur ^ 1, (kc + 1) * 32); CPC(); CPW1(); }
        else        { CPW0(); }
        __syncthreads();
        const __half* xh = sm + OFF_XH + cur * XELEMS;
        const __half* xl = sm + OFF_XL + cur * XELEMS;
        const __half* wh = sm + OFF_WH + cur * WELEMS;
#pragma unroll
        for (int ks = 0; ks < 2; ks++) {
            unsigned aH[3][4], bH[2][4], bL[2][4];
#pragma unroll
            for (int mf = 0; mf < 3; mf++)
                LDM_X4(aH[mf], (unsigned)__cvta_generic_to_shared(
                    wh + (m0 + mf * 16 + arow) * WSTRIDE + ks * 16 + acol8));
#pragma unroll
            for (int nb = 0; nb < 2; nb++) {
                LDM_X4T(bH[nb], (unsigned)__cvta_generic_to_shared(
                    xh + (ks * 16 + arow) * XSTRIDE + nw0 + nb * 16 + acol8));
                LDM_X4T(bL[nb], (unsigned)__cvta_generic_to_shared(
                    xl + (ks * 16 + arow) * XSTRIDE + nw0 + nb * 16 + acol8));
            }
#pragma unroll
            for (int mf = 0; mf < 3; mf++)
#pragma unroll
                for (int j = 0; j < 4; j++)
                    MMA_F16(c[mf][j], aH[mf],
                            bH[j >> 1][(j & 1) * 2], bH[j >> 1][(j & 1) * 2 + 1]);
#pragma unroll
            for (int mf = 0; mf < 3; mf++)
#pragma unroll
                for (int j = 0; j < 4; j++)
                    MMA_F16(c[mf][j], aH[mf],
                            bL[j >> 1][(j & 1) * 2], bL[j >> 1][(j & 1) * 2 + 1]);
        }
        __syncthreads();
    }

    int fr0 = 2 * hy;
#pragma unroll
    for (int mf = 0; mf < 3; mf++)
#pragma unroll
        for (int j = 0; j < 4; j++)
#pragma unroll
            for (int rh = 0; rh < 2; rh++) {
                float v0 = c[mf][j][rh * 2 + 0];
                float v1 = c[mf][j][rh * 2 + 1];
                int oc = oc0 + m0 + mf * 16 + (l >> 2) + 8 * rh;
                int hc = nw0 + (j >> 1) * 16 + (j & 1) * 8 + 2 * (l & 3);
                float4 v4 = make_float4(v0, v0, v1, v1);
                float* ob = out + ((size_t)b * DIMc + oc) * 65536 +
                            fr0 * 256 + 2 * hc;
                *(float4*)ob = v4;
                *(float4*)(ob + 256) = v4;
            }
}

// ---------------------------------------------------------------- launch
extern "C" void kernel_launch(void* const* d_in, const int* in_sizes, int n_in,
                              void* d_out, int out_size) {
    const float* x      = (const float*)d_in[0];
    const float* temp   = (const float*)d_in[1];
    const float* qkv_w  = (const float*)d_in[2];
    const float* dw_w   = (const float*)d_in[3];
    const float* proj_w = (const float*)d_in[4];
    const float* a1 = (const float*)d_in[5];
    const float* a2 = (const float*)d_in[6];
    const float* a3 = (const float*)d_in[7];
    const float* a4 = (const float*)d_in[8];
    float* out = (float*)d_out;

    cudaFuncSetAttribute(k_qkvpool, cudaFuncAttributeMaxDynamicSharedMemorySize,
                         SMEM_QKV_BYTES);
    cudaFuncSetAttribute(k_proj, cudaFuncAttributeMaxDynamicSharedMemorySize,
                         SMEM_PROJ_BYTES);

    k_splitX<<<Bn * DIMc, 256>>>(x);
    k_splitW<<<432, 256>>>(qkv_w, proj_w);
    k_qkvpool<<<dim3(6, 512, 4), 256, SMEM_QKV_BYTES>>>();
    k_dw<<<dim3(8, 576, 4), 256>>>(dw_w);
    k_attn<<<dim3(16, 24), 256>>>();
    k_soft<<<96, 256>>>(temp, a1, a2, a3, a4);
    k_av<<<dim3(64, 24), 256>>>();
    k_proj<<<dim3(128, 2, 4), 256, SMEM_PROJ_BYTES>>>(out);
}